// round 1
// baseline (speedup 1.0000x reference)
#include <cuda_runtime.h>
#include <cuda_bf16.h>
#include <math.h>

// Problem constants
#define BB 4
#define SS 2048
#define DD 1024
#define HH 8
#define EE 128
#define HE (HH * EE)   // 1024

#define NEG_BIG (-3.402823466e38f)

// ---------------- scratch (device globals; no allocs) ----------------
__device__ float g_qh[(size_t)BB * HH * SS * EE];  // [b,h,s,e] 32MB
__device__ float g_kh[(size_t)BB * HH * SS * EE];
__device__ float g_vh[(size_t)BB * HH * SS * EE];
__device__ float g_z [(size_t)BB * SS * HE];       // [b,s,h*E+e] 32MB

// =====================================================================
// Projection GEMM: per (b,h): C[S x E] = X[b][S x D] * W[h][D x E] * scale
// Block: 128 rows x 128 cols (E==128), BK=8, 256 threads, 8x8 per thread.
// grid = (1, S/128, B*H)
// =====================================================================
__global__ __launch_bounds__(256) void proj_kernel(
    const float* __restrict__ X, const float* __restrict__ W,
    float* __restrict__ Out, float scale)
{
    int bh = blockIdx.z;
    int b = bh >> 3, h = bh & 7;
    const float* A  = X + (size_t)b * SS * DD;
    const float* Wh = W + (size_t)h * DD * EE;
    float* C = Out + (size_t)bh * SS * EE;
    int s0 = blockIdx.y * 128;

    __shared__ float As[8][128];  // transposed: As[k][row]
    __shared__ float Bs[8][128];  // Bs[k][e]

    int tid = threadIdx.x;
    int tx = tid & 15, ty = tid >> 4;

    int arow = tid >> 1;
    int ak   = (tid & 1) * 4;
    int bk   = tid >> 5;
    int be   = (tid & 31) * 4;

    float acc[8][8];
#pragma unroll
    for (int i = 0; i < 8; i++)
#pragma unroll
        for (int j = 0; j < 8; j++) acc[i][j] = 0.f;

    for (int k0 = 0; k0 < DD; k0 += 8) {
        float4 a4 = *(const float4*)(A + (size_t)(s0 + arow) * DD + k0 + ak);
        As[ak + 0][arow] = a4.x;
        As[ak + 1][arow] = a4.y;
        As[ak + 2][arow] = a4.z;
        As[ak + 3][arow] = a4.w;
        *(float4*)(&Bs[bk][be]) = *(const float4*)(Wh + (size_t)(k0 + bk) * EE + be);
        __syncthreads();
#pragma unroll
        for (int kk = 0; kk < 8; kk++) {
            float a[8], bv[8];
            *(float4*)(a)      = *(const float4*)(&As[kk][ty * 8]);
            *(float4*)(a + 4)  = *(const float4*)(&As[kk][ty * 8 + 4]);
            *(float4*)(bv)     = *(const float4*)(&Bs[kk][tx * 8]);
            *(float4*)(bv + 4) = *(const float4*)(&Bs[kk][tx * 8 + 4]);
#pragma unroll
            for (int i = 0; i < 8; i++)
#pragma unroll
                for (int j = 0; j < 8; j++) acc[i][j] += a[i] * bv[j];
        }
        __syncthreads();
    }
#pragma unroll
    for (int i = 0; i < 8; i++) {
        float* crow = C + (size_t)(s0 + ty * 8 + i) * EE + tx * 8;
        float4 v0 = make_float4(acc[i][0] * scale, acc[i][1] * scale,
                                acc[i][2] * scale, acc[i][3] * scale);
        float4 v1 = make_float4(acc[i][4] * scale, acc[i][5] * scale,
                                acc[i][6] * scale, acc[i][7] * scale);
        *(float4*)(crow)     = v0;
        *(float4*)(crow + 4) = v1;
    }
}

// =====================================================================
// Output GEMM: Out[B*S x D] = Z[B*S x HE] * Wo[HE x D] + bo
// grid = (D/128, B*S/128)
// =====================================================================
__global__ __launch_bounds__(256) void out_gemm_kernel(
    const float* __restrict__ Z, const float* __restrict__ Wo,
    const float* __restrict__ bo, float* __restrict__ Out)
{
    int row0 = blockIdx.y * 128;
    int col0 = blockIdx.x * 128;

    __shared__ float As[8][128];
    __shared__ float Bs[8][128];

    int tid = threadIdx.x;
    int tx = tid & 15, ty = tid >> 4;

    int arow = tid >> 1;
    int ak   = (tid & 1) * 4;
    int bk   = tid >> 5;
    int be   = (tid & 31) * 4;

    float acc[8][8];
#pragma unroll
    for (int i = 0; i < 8; i++)
#pragma unroll
        for (int j = 0; j < 8; j++) acc[i][j] = 0.f;

    for (int k0 = 0; k0 < HE; k0 += 8) {
        float4 a4 = *(const float4*)(Z + (size_t)(row0 + arow) * HE + k0 + ak);
        As[ak + 0][arow] = a4.x;
        As[ak + 1][arow] = a4.y;
        As[ak + 2][arow] = a4.z;
        As[ak + 3][arow] = a4.w;
        *(float4*)(&Bs[bk][be]) =
            *(const float4*)(Wo + (size_t)(k0 + bk) * DD + col0 + be);
        __syncthreads();
#pragma unroll
        for (int kk = 0; kk < 8; kk++) {
            float a[8], bv[8];
            *(float4*)(a)      = *(const float4*)(&As[kk][ty * 8]);
            *(float4*)(a + 4)  = *(const float4*)(&As[kk][ty * 8 + 4]);
            *(float4*)(bv)     = *(const float4*)(&Bs[kk][tx * 8]);
            *(float4*)(bv + 4) = *(const float4*)(&Bs[kk][tx * 8 + 4]);
#pragma unroll
            for (int i = 0; i < 8; i++)
#pragma unroll
                for (int j = 0; j < 8; j++) acc[i][j] += a[i] * bv[j];
        }
        __syncthreads();
    }
#pragma unroll
    for (int i = 0; i < 8; i++) {
        float* crow = Out + (size_t)(row0 + ty * 8 + i) * DD + col0 + tx * 8;
        float b0 = bo[col0 + tx * 8 + 0], b1 = bo[col0 + tx * 8 + 1];
        float b2 = bo[col0 + tx * 8 + 2], b3 = bo[col0 + tx * 8 + 3];
        float b4 = bo[col0 + tx * 8 + 4], b5 = bo[col0 + tx * 8 + 5];
        float b6 = bo[col0 + tx * 8 + 6], b7 = bo[col0 + tx * 8 + 7];
        float4 v0 = make_float4(acc[i][0] + b0, acc[i][1] + b1,
                                acc[i][2] + b2, acc[i][3] + b3);
        float4 v1 = make_float4(acc[i][4] + b4, acc[i][5] + b5,
                                acc[i][6] + b6, acc[i][7] + b7);
        *(float4*)(crow)     = v0;
        *(float4*)(crow + 4) = v1;
    }
}

// =====================================================================
// Flash attention per (b,h): online softmax over S=2048 keys.
// BM=64 query rows per block, BN=64 key rows per tile, full E=128 in smem.
// 256 threads. Dynamic smem.
// grid = (S/64, B*H)
// =====================================================================
#define BM 64
#define BN 64
#define KP 132   // padded float stride for 128-wide tiles (132 % 32 == 4)
#define SP 68    // padded stride for 64-wide score tile

extern "C" __global__ __launch_bounds__(256) void flash_kernel(
    const float* __restrict__ qh, const float* __restrict__ kh,
    const float* __restrict__ vh, float* __restrict__ z)
{
    extern __shared__ float sm[];
    float* Qs   = sm;                 // 64*132
    float* Ks   = Qs + BM * KP;       // 64*132
    float* Vs   = Ks + BN * KP;       // 64*132
    float* Ssm  = Vs + BN * KP;       // 64*68
    float* mrow = Ssm + BM * SP;      // 64
    float* lrow = mrow + BM;          // 64
    float* arow = lrow + BM;          // 64

    int bh = blockIdx.y;
    int b = bh >> 3, h = bh & 7;
    int q0 = blockIdx.x * BM;

    const float* Qg = qh + ((size_t)bh * SS + q0) * EE;
    const float* Kg = kh + (size_t)bh * SS * EE;
    const float* Vg = vh + (size_t)bh * SS * EE;

    int tid = threadIdx.x;

    // load Q tile (already scaled by 1/sqrt(E) in projection)
    for (int i = tid; i < BM * 32; i += 256) {
        int r = i >> 5, c4 = (i & 31) * 4;
        *(float4*)(Qs + r * KP + c4) = *(const float4*)(Qg + (size_t)r * EE + c4);
    }
    if (tid < BM) { mrow[tid] = NEG_BIG; lrow[tid] = 0.f; }

    float o[32];
#pragma unroll
    for (int i = 0; i < 32; i++) o[i] = 0.f;

    int rl = tid >> 4;        // score row lane  (rows rl + 16*i)
    int cl = tid & 15;        // score col lane  (cols cl + 16*j)
    int srow = tid >> 2;      // softmax / O row (0..63)
    int spart = tid & 3;      // softmax column quarter
    int oc = (tid & 3) * 4;   // O e-offset base (interleaved, stride 16)

    for (int kt = 0; kt < SS / BN; kt++) {
        __syncthreads();
        const float* Kgt = Kg + (size_t)kt * BN * EE;
        const float* Vgt = Vg + (size_t)kt * BN * EE;
        for (int i = tid; i < BN * 32; i += 256) {
            int r = i >> 5, c4 = (i & 31) * 4;
            *(float4*)(Ks + r * KP + c4) = *(const float4*)(Kgt + (size_t)r * EE + c4);
            *(float4*)(Vs + r * KP + c4) = *(const float4*)(Vgt + (size_t)r * EE + c4);
        }
        __syncthreads();

        // ---- scores: each thread 4x4 micro-tile (strided rows/cols) ----
        float sc[4][4];
#pragma unroll
        for (int i = 0; i < 4; i++)
#pragma unroll
            for (int j = 0; j < 4; j++) sc[i][j] = 0.f;

        for (int e = 0; e < EE; e += 4) {
            float4 qv[4], kv[4];
#pragma unroll
            for (int i = 0; i < 4; i++)
                qv[i] = *(const float4*)(Qs + (rl + 16 * i) * KP + e);
#pragma unroll
            for (int j = 0; j < 4; j++)
                kv[j] = *(const float4*)(Ks + (cl + 16 * j) * KP + e);
#pragma unroll
            for (int i = 0; i < 4; i++)
#pragma unroll
                for (int j = 0; j < 4; j++)
                    sc[i][j] += qv[i].x * kv[j].x + qv[i].y * kv[j].y +
                                qv[i].z * kv[j].z + qv[i].w * kv[j].w;
        }
#pragma unroll
        for (int i = 0; i < 4; i++)
#pragma unroll
            for (int j = 0; j < 4; j++)
                Ssm[(rl + 16 * i) * SP + cl + 16 * j] = sc[i][j];
        __syncthreads();

        // ---- online softmax (4 lanes per row) ----
        {
            float vmax = NEG_BIG;
#pragma unroll
            for (int j = 0; j < 16; j++)
                vmax = fmaxf(vmax, Ssm[srow * SP + spart * 16 + j]);
            vmax = fmaxf(vmax, __shfl_xor_sync(0xffffffffu, vmax, 1));
            vmax = fmaxf(vmax, __shfl_xor_sync(0xffffffffu, vmax, 2));
            float m_old = mrow[srow];
            float m_new = fmaxf(m_old, vmax);
            float sum = 0.f;
#pragma unroll
            for (int j = 0; j < 16; j++) {
                float p = __expf(Ssm[srow * SP + spart * 16 + j] - m_new);
                Ssm[srow * SP + spart * 16 + j] = p;
                sum += p;
            }
            sum += __shfl_xor_sync(0xffffffffu, sum, 1);
            sum += __shfl_xor_sync(0xffffffffu, sum, 2);
            if (spart == 0) {
                float al = expf(m_old - m_new);
                arow[srow] = al;
                mrow[srow] = m_new;
                lrow[srow] = lrow[srow] * al + sum;
            }
        }
        __syncthreads();

        // ---- O accumulation: thread owns (row srow, 32 interleaved e) ----
        {
            float al = arow[srow];
#pragma unroll
            for (int i = 0; i < 32; i++) o[i] *= al;
            for (int j = 0; j < BN; j++) {
                float p = Ssm[srow * SP + j];
                const float* vr = Vs + j * KP;
#pragma unroll
                for (int ii = 0; ii < 8; ii++) {
                    float4 v4 = *(const float4*)(vr + oc + 16 * ii);
                    o[ii * 4 + 0] += p * v4.x;
                    o[ii * 4 + 1] += p * v4.y;
                    o[ii * 4 + 2] += p * v4.z;
                    o[ii * 4 + 3] += p * v4.w;
                }
            }
        }
    }

    // ---- finalize: divide by l and write to z [b, s, h*E + e] ----
    float linv = 1.f / lrow[srow];
    float* zr = z + ((size_t)(b * SS + q0 + srow)) * HE + h * EE;
#pragma unroll
    for (int ii = 0; ii < 8; ii++) {
        float4 v4 = make_float4(o[ii * 4 + 0] * linv, o[ii * 4 + 1] * linv,
                                o[ii * 4 + 2] * linv, o[ii * 4 + 3] * linv);
        *(float4*)(zr + oc + 16 * ii) = v4;
    }
}

// =====================================================================
// launch
// =====================================================================
extern "C" void kernel_launch(void* const* d_in, const int* in_sizes, int n_in,
                              void* d_out, int out_size)
{
    const float* q  = (const float*)d_in[0];
    const float* k  = (const float*)d_in[1];
    const float* v  = (const float*)d_in[2];
    const float* Wq = (const float*)d_in[3];
    const float* Wk = (const float*)d_in[4];
    const float* Wv = (const float*)d_in[5];
    const float* Wo = (const float*)d_in[6];
    const float* bo = (const float*)d_in[7];
    float* out = (float*)d_out;

    float* qh; cudaGetSymbolAddress((void**)&qh, g_qh);
    float* kh; cudaGetSymbolAddress((void**)&kh, g_kh);
    float* vh; cudaGetSymbolAddress((void**)&vh, g_vh);
    float* z;  cudaGetSymbolAddress((void**)&z,  g_z);

    const int flash_smem = (3 * BM * KP + BM * SP + 3 * BM) * (int)sizeof(float);
    cudaFuncSetAttribute(flash_kernel,
                         cudaFuncAttributeMaxDynamicSharedMemorySize, flash_smem);

    float qscale = 1.0f / sqrtf((float)EE);

    dim3 pgrid(1, SS / 128, BB * HH);
    proj_kernel<<<pgrid, 256>>>(q, Wq, qh, qscale);
    proj_kernel<<<pgrid, 256>>>(k, Wk, kh, 1.0f);
    proj_kernel<<<pgrid, 256>>>(v, Wv, vh, 1.0f);

    dim3 fgrid(SS / BM, BB * HH);
    flash_kernel<<<fgrid, 256, flash_smem>>>(qh, kh, vh, z);

    dim3 ogrid(DD / 128, (BB * SS) / 128);
    out_gemm_kernel<<<ogrid, 256>>>(z, Wo, bo, out);
}

// round 2
// speedup vs baseline: 4.2583x; 4.2583x over previous
#include <cuda_runtime.h>
#include <cuda_bf16.h>
#include <math.h>

// Problem constants
#define BB 4
#define SS 2048
#define DD 1024
#define HH 8
#define EE 128
#define HE (HH * EE)   // 1024

#define NEG_BIG (-3.402823466e38f)

// ---------------- scratch (device globals; no allocs) ----------------
__device__ float g_qh[(size_t)BB * HH * SS * EE];  // [b,h,s,e] 32MB
__device__ float g_kh[(size_t)BB * HH * SS * EE];
__device__ float g_vh[(size_t)BB * HH * SS * EE];
__device__ float g_z [(size_t)BB * SS * HE];       // [b,s,h*E+e] 32MB

// ---------------- helpers ----------------
__device__ __forceinline__ unsigned f2tf(float x) {
    unsigned u;
    asm("cvt.rna.tf32.f32 %0, %1;" : "=r"(u) : "f"(x));
    return u;
}

__device__ __forceinline__ void mma_tf32(float& d0, float& d1, float& d2, float& d3,
                                         unsigned a0, unsigned a1, unsigned a2, unsigned a3,
                                         unsigned b0, unsigned b1)
{
    asm volatile(
        "mma.sync.aligned.m16n8k8.row.col.f32.tf32.tf32.f32 "
        "{%0,%1,%2,%3}, {%4,%5,%6,%7}, {%8,%9}, {%0,%1,%2,%3};\n"
        : "+f"(d0), "+f"(d1), "+f"(d2), "+f"(d3)
        : "r"(a0), "r"(a1), "r"(a2), "r"(a3), "r"(b0), "r"(b1));
}

// =====================================================================
// Projection GEMM (tensor cores, tf32):
//   per (b,h): C[S x 128] = X[b][S x 1024] * W[h][1024 x 128] * scale
// Block: 128x128 tile, KC=32, 256 threads (8 warps, warp tile 32x64).
// grid = (1, S/128, B*H)
// =====================================================================
#define ASTR 36    // padded k-stride for A smem (KC=32+4) -> frag reads conflict-free
#define BSTR 136   // padded n-stride for B smem (128+8)   -> frag reads conflict-free

__global__ __launch_bounds__(256, 2) void proj_tc(
    const float* __restrict__ X, const float* __restrict__ W,
    float* __restrict__ Out, float scale)
{
    __shared__ unsigned As[128 * ASTR];
    __shared__ unsigned Bs[32 * BSTR];

    int bh = blockIdx.z;
    int b = bh >> 3, h = bh & 7;
    const float* A  = X + (size_t)b * SS * DD;
    const float* Bw = W + (size_t)h * DD * EE;
    float* C = Out + (size_t)bh * SS * EE;
    int s0 = blockIdx.y * 128;

    int tid = threadIdx.x;
    int warp = tid >> 5, lane = tid & 31;
    int g = lane >> 2, c = lane & 3;
    int wm = warp >> 1, wn = warp & 1;

    float acc[2][8][4];
#pragma unroll
    for (int i = 0; i < 2; i++)
#pragma unroll
        for (int j = 0; j < 8; j++)
#pragma unroll
            for (int t = 0; t < 4; t++) acc[i][j][t] = 0.f;

    for (int k0 = 0; k0 < DD; k0 += 32) {
        // stage A tile 128x32
#pragma unroll
        for (int it = 0; it < 4; it++) {
            int idx = tid + it * 256;
            int r = idx >> 3, c4 = (idx & 7) * 4;
            float4 v = *(const float4*)(A + (size_t)(s0 + r) * DD + k0 + c4);
            unsigned* dst = &As[r * ASTR + c4];
            dst[0] = f2tf(v.x); dst[1] = f2tf(v.y);
            dst[2] = f2tf(v.z); dst[3] = f2tf(v.w);
        }
        // stage B tile 32x128
#pragma unroll
        for (int it = 0; it < 4; it++) {
            int idx = tid + it * 256;
            int r = idx >> 5, c4 = (idx & 31) * 4;
            float4 v = *(const float4*)(Bw + (size_t)(k0 + r) * EE + c4);
            unsigned* dst = &Bs[r * BSTR + c4];
            dst[0] = f2tf(v.x); dst[1] = f2tf(v.y);
            dst[2] = f2tf(v.z); dst[3] = f2tf(v.w);
        }
        __syncthreads();

#pragma unroll
        for (int kk = 0; kk < 32; kk += 8) {
            unsigned a[2][4];
#pragma unroll
            for (int mi = 0; mi < 2; mi++) {
                int base = (wm * 32 + mi * 16 + g) * ASTR + kk + c;
                a[mi][0] = As[base];
                a[mi][1] = As[base + 8 * ASTR];
                a[mi][2] = As[base + 4];
                a[mi][3] = As[base + 8 * ASTR + 4];
            }
            unsigned bf[8][2];
#pragma unroll
            for (int jt = 0; jt < 8; jt++) {
                int base = (kk + c) * BSTR + wn * 64 + jt * 8 + g;
                bf[jt][0] = Bs[base];
                bf[jt][1] = Bs[base + 4 * BSTR];
            }
#pragma unroll
            for (int mi = 0; mi < 2; mi++)
#pragma unroll
                for (int jt = 0; jt < 8; jt++)
                    mma_tf32(acc[mi][jt][0], acc[mi][jt][1], acc[mi][jt][2], acc[mi][jt][3],
                             a[mi][0], a[mi][1], a[mi][2], a[mi][3],
                             bf[jt][0], bf[jt][1]);
        }
        __syncthreads();
    }

    // epilogue
#pragma unroll
    for (int mi = 0; mi < 2; mi++) {
        int r = s0 + wm * 32 + mi * 16 + g;
#pragma unroll
        for (int jt = 0; jt < 8; jt++) {
            int col = wn * 64 + jt * 8 + 2 * c;
            float2 v0 = make_float2(acc[mi][jt][0] * scale, acc[mi][jt][1] * scale);
            float2 v1 = make_float2(acc[mi][jt][2] * scale, acc[mi][jt][3] * scale);
            *(float2*)(C + (size_t)r * EE + col)       = v0;
            *(float2*)(C + (size_t)(r + 8) * EE + col) = v1;
        }
    }
}

// =====================================================================
// Output GEMM (tensor cores): Out[B*S x 1024] = Z[B*S x 1024]*Wo + bo
// grid = (D/128, B*S/128)
// =====================================================================
__global__ __launch_bounds__(256, 2) void out_tc(
    const float* __restrict__ Z, const float* __restrict__ Wo,
    const float* __restrict__ bo, float* __restrict__ Out)
{
    __shared__ unsigned As[128 * ASTR];
    __shared__ unsigned Bs[32 * BSTR];

    int row0 = blockIdx.y * 128;
    int col0 = blockIdx.x * 128;

    int tid = threadIdx.x;
    int warp = tid >> 5, lane = tid & 31;
    int g = lane >> 2, c = lane & 3;
    int wm = warp >> 1, wn = warp & 1;

    float acc[2][8][4];
#pragma unroll
    for (int i = 0; i < 2; i++)
#pragma unroll
        for (int j = 0; j < 8; j++)
#pragma unroll
            for (int t = 0; t < 4; t++) acc[i][j][t] = 0.f;

    for (int k0 = 0; k0 < HE; k0 += 32) {
#pragma unroll
        for (int it = 0; it < 4; it++) {
            int idx = tid + it * 256;
            int r = idx >> 3, c4 = (idx & 7) * 4;
            float4 v = *(const float4*)(Z + (size_t)(row0 + r) * HE + k0 + c4);
            unsigned* dst = &As[r * ASTR + c4];
            dst[0] = f2tf(v.x); dst[1] = f2tf(v.y);
            dst[2] = f2tf(v.z); dst[3] = f2tf(v.w);
        }
#pragma unroll
        for (int it = 0; it < 4; it++) {
            int idx = tid + it * 256;
            int r = idx >> 5, c4 = (idx & 31) * 4;
            float4 v = *(const float4*)(Wo + (size_t)(k0 + r) * DD + col0 + c4);
            unsigned* dst = &Bs[r * BSTR + c4];
            dst[0] = f2tf(v.x); dst[1] = f2tf(v.y);
            dst[2] = f2tf(v.z); dst[3] = f2tf(v.w);
        }
        __syncthreads();

#pragma unroll
        for (int kk = 0; kk < 32; kk += 8) {
            unsigned a[2][4];
#pragma unroll
            for (int mi = 0; mi < 2; mi++) {
                int base = (wm * 32 + mi * 16 + g) * ASTR + kk + c;
                a[mi][0] = As[base];
                a[mi][1] = As[base + 8 * ASTR];
                a[mi][2] = As[base + 4];
                a[mi][3] = As[base + 8 * ASTR + 4];
            }
            unsigned bf[8][2];
#pragma unroll
            for (int jt = 0; jt < 8; jt++) {
                int base = (kk + c) * BSTR + wn * 64 + jt * 8 + g;
                bf[jt][0] = Bs[base];
                bf[jt][1] = Bs[base + 4 * BSTR];
            }
#pragma unroll
            for (int mi = 0; mi < 2; mi++)
#pragma unroll
                for (int jt = 0; jt < 8; jt++)
                    mma_tf32(acc[mi][jt][0], acc[mi][jt][1], acc[mi][jt][2], acc[mi][jt][3],
                             a[mi][0], a[mi][1], a[mi][2], a[mi][3],
                             bf[jt][0], bf[jt][1]);
        }
        __syncthreads();
    }

#pragma unroll
    for (int mi = 0; mi < 2; mi++) {
        int r = row0 + wm * 32 + mi * 16 + g;
#pragma unroll
        for (int jt = 0; jt < 8; jt++) {
            int col = col0 + wn * 64 + jt * 8 + 2 * c;
            float b0 = bo[col], b1 = bo[col + 1];
            float2 v0 = make_float2(acc[mi][jt][0] + b0, acc[mi][jt][1] + b1);
            float2 v1 = make_float2(acc[mi][jt][2] + b0, acc[mi][jt][3] + b1);
            *(float2*)(Out + (size_t)r * DD + col)       = v0;
            *(float2*)(Out + (size_t)(r + 8) * DD + col) = v1;
        }
    }
}

// =====================================================================
// Flash attention (tensor cores, tf32), per (b,h).
// BM=128 q rows / block, BN=64 keys / tile, online softmax.
// 256 threads (8 warps). grid = (S/128, B*H).
// smem strides chosen for conflict-free fragment reads:
//   QK rows stride 132 (A-pattern), V stride 136 (B-pattern), P stride 68.
// =====================================================================
#define FBM 128
#define FBN 64
#define QSTR 132
#define VSTR 136
#define PSTR 68

extern "C" __global__ __launch_bounds__(256, 1) void flash_tc(
    const float* __restrict__ qh, const float* __restrict__ kh,
    const float* __restrict__ vh, float* __restrict__ z)
{
    extern __shared__ unsigned sm[];
    unsigned* Qs = sm;                       // 128*132
    unsigned* Ks = Qs + FBM * QSTR;          // 64*132
    unsigned* Vs = Ks + FBN * QSTR;          // 64*136
    float*    Sf = (float*)(Vs + FBN * VSTR);// 128*68 (scores fp32, then P tf32)
    unsigned* Su = (unsigned*)Sf;
    float* mrow = Sf + FBM * PSTR;           // 128
    float* lrow = mrow + FBM;                // 128
    float* arow = lrow + FBM;                // 128

    int bh = blockIdx.y;
    int b = bh >> 3, h = bh & 7;
    int q0 = blockIdx.x * FBM;

    const float* Qg = qh + ((size_t)bh * SS + q0) * EE;
    const float* Kg = kh + (size_t)bh * SS * EE;
    const float* Vg = vh + (size_t)bh * SS * EE;

    int tid = threadIdx.x;
    int warp = tid >> 5, lane = tid & 31;
    int g = lane >> 2, c = lane & 3;
    int wm = warp >> 1, wn = warp & 1;

    // stage Q (128x128) once
#pragma unroll
    for (int it = 0; it < 16; it++) {
        int idx = tid + it * 256;
        int r = idx >> 5, c4 = (idx & 31) * 4;
        float4 v = *(const float4*)(Qg + (size_t)r * EE + c4);
        unsigned* dst = &Qs[r * QSTR + c4];
        dst[0] = f2tf(v.x); dst[1] = f2tf(v.y);
        dst[2] = f2tf(v.z); dst[3] = f2tf(v.w);
    }
    if (tid < FBM) { mrow[tid] = NEG_BIG; lrow[tid] = 0.f; }

    float o[2][8][4];
#pragma unroll
    for (int i = 0; i < 2; i++)
#pragma unroll
        for (int j = 0; j < 8; j++)
#pragma unroll
            for (int t = 0; t < 4; t++) o[i][j][t] = 0.f;

    int srow = tid >> 1;       // softmax row (0..127)
    int shalf = tid & 1;       // which half of 64 cols

    for (int kt = 0; kt < SS / FBN; kt++) {
        __syncthreads();  // prev PV done reading Vs/Su
        const float* Kgt = Kg + (size_t)kt * FBN * EE;
        const float* Vgt = Vg + (size_t)kt * FBN * EE;
#pragma unroll
        for (int it = 0; it < 8; it++) {
            int idx = tid + it * 256;
            int r = idx >> 5, c4 = (idx & 31) * 4;
            float4 kv = *(const float4*)(Kgt + (size_t)r * EE + c4);
            unsigned* kd = &Ks[r * QSTR + c4];
            kd[0] = f2tf(kv.x); kd[1] = f2tf(kv.y);
            kd[2] = f2tf(kv.z); kd[3] = f2tf(kv.w);
            float4 vv = *(const float4*)(Vgt + (size_t)r * EE + c4);
            unsigned* vd = &Vs[r * VSTR + c4];
            vd[0] = f2tf(vv.x); vd[1] = f2tf(vv.y);
            vd[2] = f2tf(vv.z); vd[3] = f2tf(vv.w);
        }
        __syncthreads();

        // ---- scores: C[128x64] = Q * K^T; warp tile 32x32 ----
        float sc[2][4][4];
#pragma unroll
        for (int i = 0; i < 2; i++)
#pragma unroll
            for (int j = 0; j < 4; j++)
#pragma unroll
                for (int t = 0; t < 4; t++) sc[i][j][t] = 0.f;

#pragma unroll
        for (int kk = 0; kk < EE; kk += 8) {
            unsigned a[2][4];
#pragma unroll
            for (int mi = 0; mi < 2; mi++) {
                int base = (wm * 32 + mi * 16 + g) * QSTR + kk + c;
                a[mi][0] = Qs[base];
                a[mi][1] = Qs[base + 8 * QSTR];
                a[mi][2] = Qs[base + 4];
                a[mi][3] = Qs[base + 8 * QSTR + 4];
            }
            unsigned bf[4][2];
#pragma unroll
            for (int jt = 0; jt < 4; jt++) {
                int base = (wn * 32 + jt * 8 + g) * QSTR + kk + c;
                bf[jt][0] = Ks[base];
                bf[jt][1] = Ks[base + 4];
            }
#pragma unroll
            for (int mi = 0; mi < 2; mi++)
#pragma unroll
                for (int jt = 0; jt < 4; jt++)
                    mma_tf32(sc[mi][jt][0], sc[mi][jt][1], sc[mi][jt][2], sc[mi][jt][3],
                             a[mi][0], a[mi][1], a[mi][2], a[mi][3],
                             bf[jt][0], bf[jt][1]);
        }
        // write scores to smem
#pragma unroll
        for (int mi = 0; mi < 2; mi++) {
            int r = wm * 32 + mi * 16 + g;
#pragma unroll
            for (int jt = 0; jt < 4; jt++) {
                int col = wn * 32 + jt * 8 + 2 * c;
                *(float2*)(Sf + r * PSTR + col)       = make_float2(sc[mi][jt][0], sc[mi][jt][1]);
                *(float2*)(Sf + (r + 8) * PSTR + col) = make_float2(sc[mi][jt][2], sc[mi][jt][3]);
            }
        }
        __syncthreads();

        // ---- online softmax (2 lanes per row), write P as tf32 ----
        {
            float* row = Sf + srow * PSTR + shalf * 32;
            float vmax = NEG_BIG;
#pragma unroll
            for (int j = 0; j < 32; j++) vmax = fmaxf(vmax, row[j]);
            vmax = fmaxf(vmax, __shfl_xor_sync(0xffffffffu, vmax, 1));
            float m_old = mrow[srow];
            float m_new = fmaxf(m_old, vmax);
            float sum = 0.f;
            unsigned* rowu = Su + srow * PSTR + shalf * 32;
#pragma unroll
            for (int j = 0; j < 32; j++) {
                float p = __expf(row[j] - m_new);
                sum += p;
                rowu[j] = f2tf(p);
            }
            sum += __shfl_xor_sync(0xffffffffu, sum, 1);
            if (shalf == 0) {
                float al = expf(m_old - m_new);
                arow[srow] = al;
                mrow[srow] = m_new;
                lrow[srow] = lrow[srow] * al + sum;
            }
        }
        __syncthreads();

        // ---- O rescale + PV: O[128x128] += P[128x64] * V[64x128] ----
        {
            int r0 = wm * 32 + g;
            float al0 = arow[r0];
            float al1 = arow[r0 + 8];
            float al2 = arow[r0 + 16];
            float al3 = arow[r0 + 24];
#pragma unroll
            for (int jt = 0; jt < 8; jt++) {
                o[0][jt][0] *= al0; o[0][jt][1] *= al0;
                o[0][jt][2] *= al1; o[0][jt][3] *= al1;
                o[1][jt][0] *= al2; o[1][jt][1] *= al2;
                o[1][jt][2] *= al3; o[1][jt][3] *= al3;
            }
#pragma unroll
            for (int kk = 0; kk < FBN; kk += 8) {
                unsigned a[2][4];
#pragma unroll
                for (int mi = 0; mi < 2; mi++) {
                    int base = (wm * 32 + mi * 16 + g) * PSTR + kk + c;
                    a[mi][0] = Su[base];
                    a[mi][1] = Su[base + 8 * PSTR];
                    a[mi][2] = Su[base + 4];
                    a[mi][3] = Su[base + 8 * PSTR + 4];
                }
                unsigned bf[8][2];
#pragma unroll
                for (int jt = 0; jt < 8; jt++) {
                    int base = (kk + c) * VSTR + wn * 64 + jt * 8 + g;
                    bf[jt][0] = Vs[base];
                    bf[jt][1] = Vs[base + 4 * VSTR];
                }
#pragma unroll
                for (int mi = 0; mi < 2; mi++)
#pragma unroll
                    for (int jt = 0; jt < 8; jt++)
                        mma_tf32(o[mi][jt][0], o[mi][jt][1], o[mi][jt][2], o[mi][jt][3],
                                 a[mi][0], a[mi][1], a[mi][2], a[mi][3],
                                 bf[jt][0], bf[jt][1]);
            }
        }
    }

    // ---- finalize: divide by l, write to z[b, s, h*E + e] ----
    __syncthreads();
    {
        int r0 = wm * 32 + g;
        float li0 = 1.f / lrow[r0];
        float li1 = 1.f / lrow[r0 + 8];
        float li2 = 1.f / lrow[r0 + 16];
        float li3 = 1.f / lrow[r0 + 24];
#pragma unroll
        for (int mi = 0; mi < 2; mi++) {
            int r = wm * 32 + mi * 16 + g;
            float lia = (mi == 0) ? li0 : li2;
            float lib = (mi == 0) ? li1 : li3;
            float* z0 = z + ((size_t)(b * SS + q0 + r)) * HE + h * EE;
            float* z1 = z + ((size_t)(b * SS + q0 + r + 8)) * HE + h * EE;
#pragma unroll
            for (int jt = 0; jt < 8; jt++) {
                int col = wn * 64 + jt * 8 + 2 * c;
                *(float2*)(z0 + col) = make_float2(o[mi][jt][0] * lia, o[mi][jt][1] * lia);
                *(float2*)(z1 + col) = make_float2(o[mi][jt][2] * lib, o[mi][jt][3] * lib);
            }
        }
    }
}

// =====================================================================
// launch
// =====================================================================
extern "C" void kernel_launch(void* const* d_in, const int* in_sizes, int n_in,
                              void* d_out, int out_size)
{
    const float* q  = (const float*)d_in[0];
    const float* k  = (const float*)d_in[1];
    const float* v  = (const float*)d_in[2];
    const float* Wq = (const float*)d_in[3];
    const float* Wk = (const float*)d_in[4];
    const float* Wv = (const float*)d_in[5];
    const float* Wo = (const float*)d_in[6];
    const float* bo = (const float*)d_in[7];
    float* out = (float*)d_out;

    float* qh; cudaGetSymbolAddress((void**)&qh, g_qh);
    float* kh; cudaGetSymbolAddress((void**)&kh, g_kh);
    float* vh; cudaGetSymbolAddress((void**)&vh, g_vh);
    float* z;  cudaGetSymbolAddress((void**)&z,  g_z);

    const int flash_smem =
        (FBM * QSTR + FBN * QSTR + FBN * VSTR + FBM * PSTR + 3 * FBM) * (int)sizeof(float);
    cudaFuncSetAttribute(flash_tc,
                         cudaFuncAttributeMaxDynamicSharedMemorySize, flash_smem);

    float qscale = 1.0f / sqrtf((float)EE);

    dim3 pgrid(1, SS / 128, BB * HH);
    proj_tc<<<pgrid, 256>>>(q, Wq, qh, qscale);
    proj_tc<<<pgrid, 256>>>(k, Wk, kh, 1.0f);
    proj_tc<<<pgrid, 256>>>(v, Wv, vh, 1.0f);

    dim3 fgrid(SS / FBM, BB * HH);
    flash_tc<<<fgrid, 256, flash_smem>>>(qh, kh, vh, z);

    dim3 ogrid(DD / 128, (BB * SS) / 128);
    out_tc<<<ogrid, 256>>>(z, Wo, bo, out);
}